// round 8
// baseline (speedup 1.0000x reference)
#include <cuda_runtime.h>
#include <cuda_fp16.h>
#include <math.h>
#include <stdint.h>

// Problem constants
#define BB 32
#define NN 4096
#define DD 512
#define CC 64
#define RTOT (BB*NN)          // 131072 rows
#define MT 32                 // rows per GEMM tile
#define NTILES (RTOT/MT)      // 4096
#define DP 65                 // dots pitch in floats (conflict-free stores)
#define CHUNK 128             // rows per feature chunk
#define NCHUNK (NN/CHUNK)     // 32

// smem byte offsets
#define SM_ANCH  0                       // 64 rows x 1024 B (512 fp16, swizzled) = 65536
#define SM_X     65536                   // 2 x 32 x 1024 B = 65536
#define SM_DOTS  131072                  // 2 buf x 2 kh x 32 x DP f32 = 33280
#define SM_ANORM (SM_DOTS + 33280)       // 64 f32
#define SM_NORM  (SM_ANORM + 256)        // 2 x 32 f32
#define SM_MASK  (SM_NORM + 256)         // 32 i32
#define SM_TOTAL (SM_MASK + 128)         // 164992 B

// Device scratch (allocation-free rule: __device__ globals)
__device__ float g_sw[(size_t)RTOT*CC];          // score*invnorm*valid, 32 MiB
__device__ int   g_counts[BB*CC];
__device__ int   g_index[BB];
__device__ float g_part[(size_t)BB*NCHUNK*DD];   // 2 MiB

// mask may be int64 (jax x64) or int32. Values in [1,4096]: if int64 LE,
// word 1 (high half of elem 0) is 0.
__device__ __forceinline__ int decode_mask(const int* mr, int b) {
    return (mr[1] == 0) ? mr[2*b] : mr[b];
}

__device__ __forceinline__ unsigned h2u(float a, float b) {
    __half2 h = __floats2half2_rn(a, b);
    return *(unsigned*)&h;
}

__device__ __forceinline__ uint32_t smem_u32(const void* p) {
    uint32_t a;
    asm("{ .reg .u64 t; cvta.to.shared.u64 t, %1; cvt.u32.u64 %0, t; }" : "=r"(a) : "l"(p));
    return a;
}

__device__ __forceinline__ void ldsm_x4(unsigned& r0, unsigned& r1, unsigned& r2,
                                        unsigned& r3, uint32_t addr) {
    asm volatile("ldmatrix.sync.aligned.m8n8.x4.shared.b16 {%0,%1,%2,%3}, [%4];"
                 : "=r"(r0), "=r"(r1), "=r"(r2), "=r"(r3) : "r"(addr));
}

__device__ __forceinline__ void mma_f16(float* d,
                                        unsigned a0, unsigned a1, unsigned a2, unsigned a3,
                                        unsigned b0, unsigned b1) {
    asm volatile("mma.sync.aligned.m16n8k16.row.col.f32.f16.f16.f32 "
                 "{%0,%1,%2,%3}, {%4,%5,%6,%7}, {%8,%9}, {%0,%1,%2,%3};"
                 : "+f"(d[0]), "+f"(d[1]), "+f"(d[2]), "+f"(d[3])
                 : "r"(a0), "r"(a1), "r"(a2), "r"(a3), "r"(b0), "r"(b1));
}

__global__ __launch_bounds__(512, 1)
void main_kernel(const float* __restrict__ x, const int* __restrict__ maskr,
                 const float* __restrict__ anchors) {
    extern __shared__ __align__(1024) char smem[];
    const uint32_t sb = smem_u32(smem);
    float* dots_s  = (float*)(smem + SM_DOTS);
    float* anorm_s = (float*)(smem + SM_ANORM);
    float* norm_s  = (float*)(smem + SM_NORM);
    int*   mask_s  = (int*)(smem + SM_MASK);

    const int tid  = threadIdx.x;
    const int lane = tid & 31, warp = tid >> 5;   // 16 warps

    // ---- anchors -> fp16 smem, 16B-chunk XOR swizzle: chunk' = chunk ^ (c&7) ----
    for (int i = tid; i < CC*DD; i += 512) {
        int c = i >> 9, k = i & (DD-1);
        uint32_t off = (uint32_t)(c*1024 + (((k>>3) ^ (c&7))<<4) + (k&7)*2);
        *(__half*)(smem + SM_ANCH + off) = __float2half_rn(anchors[i]);
    }
    if (tid < BB) mask_s[tid] = decode_mask(maskr, tid);
    if (tid < CC) {
        float s = 0.f;
        const float* ar = anchors + (size_t)tid*DD;
        #pragma unroll 8
        for (int k = 0; k < DD; k++) { float q = ar[k]; s = fmaf(q, q, s); }
        anorm_s[tid] = s;
    }
    __syncthreads();

    // warp decomposition: ms(2) x ns(4) x kh(2); warp = 16 rows x 16 cols x 256 k
    const int ms = warp & 1, ns = (warp >> 1) & 3, kh = warp >> 3;
    const int gid = lane >> 2, tig = lane & 3;
    const int nb0 = ns*16;

    // ldmatrix address precompute
    const int arow = ms*16 + (lane & 15);
    const uint32_t pA  = sb + SM_X + arow*1024;           // + p*32768 at use
    const int xrA = arow & 7;
    const int cA0 = kh*32 + (lane >> 4);
    const int bcol = nb0 + ((lane >> 4) << 3) + (lane & 7);
    const uint32_t pB = sb + SM_ANCH + bcol*1024;
    const int xrB = lane & 7;
    const int cB0 = kh*32 + ((lane >> 3) & 1);

    // x load/store mapping: row r = tid>>4 (0..31), chunk index base cidx = tid&15
    const int r = tid >> 4, cidx = tid & 15;

    // ---- find first valid tile, prefetch raw fp32 (8 float4 per thread) ----
    int tile = blockIdx.x;
    while (tile < NTILES) {
        int bb = (tile*MT) >> 12;
        if (((tile*MT) & (NN-1)) < mask_s[bb]) break;
        tile += gridDim.x;
    }
    float4 v[8];
    if (tile < NTILES) {
        const float4* xg = (const float4*)(x + (size_t)tile*MT*DD) + r*128;
        #pragma unroll
        for (int j = 0; j < 4; j++) {
            v[2*j]   = xg[2*(cidx + 16*j)];
            v[2*j+1] = xg[2*(cidx + 16*j) + 1];
        }
    }

    int prev = -1, prevbase = 0, prevb = 0;
    int p = 0;

    while (tile < NTILES) {
        const int rowbase = tile*MT;
        const int b = rowbase >> 12;

        // ---- convert+store x tile (swizzled fp16) + row norm ----
        float nacc = 0.f;
        {
            char* xrow = smem + SM_X + p*32768 + r*1024;
            #pragma unroll
            for (int j = 0; j < 4; j++) {
                float4 q0 = v[2*j], q1 = v[2*j+1];
                uint4 st;
                st.x = h2u(q0.x, q0.y); st.y = h2u(q0.z, q0.w);
                st.z = h2u(q1.x, q1.y); st.w = h2u(q1.z, q1.w);
                int chunk = cidx + 16*j;
                *(uint4*)(xrow + ((chunk ^ (r&7))<<4)) = st;
                nacc = fmaf(q0.x,q0.x, fmaf(q0.y,q0.y, fmaf(q0.z,q0.z, fmaf(q0.w,q0.w, nacc))));
                nacc = fmaf(q1.x,q1.x, fmaf(q1.y,q1.y, fmaf(q1.z,q1.z, fmaf(q1.w,q1.w, nacc))));
            }
        }
        #pragma unroll
        for (int o = 8; o; o >>= 1) nacc += __shfl_xor_sync(0xffffffffu, nacc, o);
        if ((lane & 15) == 0) norm_s[p*MT + r] = nacc;
        __syncthreads();   // the ONLY barrier per tile

        // ---- find + prefetch next valid tile (overlaps mma + epilogue) ----
        int nt = tile + gridDim.x;
        while (nt < NTILES) {
            int nb = (nt*MT) >> 12;
            if (((nt*MT) & (NN-1)) < mask_s[nb]) break;
            nt += gridDim.x;
        }
        if (nt < NTILES) {
            const float4* xg = (const float4*)(x + (size_t)nt*MT*DD) + r*128;
            #pragma unroll
            for (int j = 0; j < 4; j++) {
                v[2*j]   = xg[2*(cidx + 16*j)];
                v[2*j+1] = xg[2*(cidx + 16*j) + 1];
            }
        }

        // ---- mma via ldmatrix: 16 k-steps, 4 independent acc chains ----
        {
            float accE0[4]={0,0,0,0}, accE1[4]={0,0,0,0};
            float accO0[4]={0,0,0,0}, accO1[4]={0,0,0,0};
            const uint32_t pAx = pA + p*32768;
            #pragma unroll
            for (int ks = 0; ks < 16; ks += 2) {
                unsigned a0,a1,a2,a3, b0,b1,b2,b3;
                unsigned c0,c1,c2,c3, e0,e1,e2,e3;
                ldsm_x4(a0,a1,a2,a3, pAx + (((2*ks     + cA0) ^ xrA) << 4));
                ldsm_x4(b0,b1,b2,b3, pB  + (((2*ks     + cB0) ^ xrB) << 4));
                ldsm_x4(c0,c1,c2,c3, pAx + (((2*ks + 2 + cA0) ^ xrA) << 4));
                ldsm_x4(e0,e1,e2,e3, pB  + (((2*ks + 2 + cB0) ^ xrB) << 4));
                mma_f16(accE0, a0,a1,a2,a3, b0,b1);
                mma_f16(accE1, a0,a1,a2,a3, b2,b3);
                mma_f16(accO0, c0,c1,c2,c3, e0,e1);
                mma_f16(accO1, c0,c1,c2,c3, e2,e3);
            }
            float* dh = dots_s + (p*2 + kh)*MT*DP;
            const int r0 = ms*16 + gid, r1 = r0 + 8, cb = 2*tig;
            dh[r0*DP + nb0 + cb]         = accE0[0] + accO0[0];
            dh[r0*DP + nb0 + cb + 1]     = accE0[1] + accO0[1];
            dh[r1*DP + nb0 + cb]         = accE0[2] + accO0[2];
            dh[r1*DP + nb0 + cb + 1]     = accE0[3] + accO0[3];
            dh[r0*DP + nb0 + 8 + cb]     = accE1[0] + accO1[0];
            dh[r0*DP + nb0 + 8 + cb + 1] = accE1[1] + accO1[1];
            dh[r1*DP + nb0 + 8 + cb]     = accE1[2] + accO1[2];
            dh[r1*DP + nb0 + 8 + cb + 1] = accE1[3] + accO1[3];
        }

        // ---- deferred epilogue for prev tile (reads buffers p^1) ----
        if (prev >= 0) {
            const int q = p ^ 1;
            const float* ds = dots_s + q*2*MT*DP;
            #pragma unroll
            for (int u = 0; u < 2; u++) {
                const int m = warp*2 + u;
                const int row = prevbase + m;
                const int n = row & (NN-1);
                const bool valid = n < mask_s[prevb];
                const float n2  = norm_s[q*MT + m];
                const float inv = 1.f / fmaxf(sqrtf(n2), 1e-12f);
                const float sxn2 = n2 * inv * inv;
                const int cA = lane, cB = lane + 32;
                const float dA = ds[m*DP + cA] + ds[MT*DP + m*DP + cA];
                const float dB = ds[m*DP + cB] + ds[MT*DP + m*DP + cB];
                const float sqA = sxn2 + anorm_s[cA] - 2.f*dA*inv;
                const float sqB = sxn2 + anorm_s[cB] - 2.f*dB*inv;
                const float idA = rsqrtf(fmaxf(sqA, 1e-30f));
                const float idB = rsqrtf(fmaxf(sqB, 1e-30f));
                float mx = fmaxf(idA, idB);
                #pragma unroll
                for (int o = 16; o; o >>= 1) mx = fmaxf(mx, __shfl_xor_sync(0xffffffffu, mx, o));
                const float eA = __expf(idA - mx), eB = __expf(idB - mx);
                float ss = eA + eB;
                #pragma unroll
                for (int o = 16; o; o >>= 1) ss += __shfl_xor_sync(0xffffffffu, ss, o);
                const float rs = 1.f / ss;
                const size_t base = (size_t)row * CC;
                g_sw[base + cA] = valid ? eA*rs*inv : 0.f;
                g_sw[base + cB] = valid ? eB*rs*inv : 0.f;
                float bv; int bi;
                if (idB > idA) { bv = idB; bi = cB; } else { bv = idA; bi = cA; }
                #pragma unroll
                for (int o = 16; o; o >>= 1) {
                    float ov = __shfl_xor_sync(0xffffffffu, bv, o);
                    int   oi = __shfl_xor_sync(0xffffffffu, bi, o);
                    if (ov > bv || (ov == bv && oi < bi)) { bv = ov; bi = oi; }
                }
                if (lane == 0 && valid) atomicAdd(&g_counts[prevb*CC + bi], 1);
            }
        }

        prev = tile; prevbase = rowbase; prevb = b;
        tile = nt; p ^= 1;
    }

    // ---- final epilogue (last tile's dots live in buffer p^1) ----
    if (prev >= 0) {
        __syncthreads();
        const int q = p ^ 1;
        const float* ds = dots_s + q*2*MT*DP;
        #pragma unroll
        for (int u = 0; u < 2; u++) {
            const int m = warp*2 + u;
            const int row = prevbase + m;
            const int n = row & (NN-1);
            const bool valid = n < mask_s[prevb];
            const float n2  = norm_s[q*MT + m];
            const float inv = 1.f / fmaxf(sqrtf(n2), 1e-12f);
            const float sxn2 = n2 * inv * inv;
            const int cA = lane, cB = lane + 32;
            const float dA = ds[m*DP + cA] + ds[MT*DP + m*DP + cA];
            const float dB = ds[m*DP + cB] + ds[MT*DP + m*DP + cB];
            const float sqA = sxn2 + anorm_s[cA] - 2.f*dA*inv;
            const float sqB = sxn2 + anorm_s[cB] - 2.f*dB*inv;
            const float idA = rsqrtf(fmaxf(sqA, 1e-30f));
            const float idB = rsqrtf(fmaxf(sqB, 1e-30f));
            float mx = fmaxf(idA, idB);
            #pragma unroll
            for (int o = 16; o; o >>= 1) mx = fmaxf(mx, __shfl_xor_sync(0xffffffffu, mx, o));
            const float eA = __expf(idA - mx), eB = __expf(idB - mx);
            float ss = eA + eB;
            #pragma unroll
            for (int o = 16; o; o >>= 1) ss += __shfl_xor_sync(0xffffffffu, ss, o);
            const float rs = 1.f / ss;
            const size_t base = (size_t)row * CC;
            g_sw[base + cA] = valid ? eA*rs*inv : 0.f;
            g_sw[base + cB] = valid ? eB*rs*inv : 0.f;
            float bv; int bi;
            if (idB > idA) { bv = idB; bi = cB; } else { bv = idA; bi = cA; }
            #pragma unroll
            for (int o = 16; o; o >>= 1) {
                float ov = __shfl_xor_sync(0xffffffffu, bv, o);
                int   oi = __shfl_xor_sync(0xffffffffu, bi, o);
                if (ov > bv || (ov == bv && oi < bi)) { bv = ov; bi = oi; }
            }
            if (lane == 0 && valid) atomicAdd(&g_counts[prevb*CC + bi], 1);
        }
    }
}

// argmax of counts per batch; also resets counts for the next graph replay
__global__ void index_kernel() {
    __shared__ int sv[CC], si[CC];
    const int b = blockIdx.x, c = threadIdx.x;
    sv[c] = g_counts[b*CC + c]; si[c] = c;
    g_counts[b*CC + c] = 0;
    __syncthreads();
    for (int o = 32; o; o >>= 1) {
        if (c < o) {
            if (sv[c+o] > sv[c] || (sv[c+o] == sv[c] && si[c+o] < si[c])) {
                sv[c] = sv[c+o]; si[c] = si[c+o];
            }
        }
        __syncthreads();
    }
    if (c == 0) g_index[b] = si[0];
}

__global__ __launch_bounds__(256)
void feat_part_kernel(const float* __restrict__ x, const int* __restrict__ maskr) {
    const int b = blockIdx.y, ch = blockIdx.x;
    const int tid = threadIdx.x;
    __shared__ float w_s[CHUNK];
    __shared__ int s_idx, s_nv;
    if (tid == 0) {
        s_idx = g_index[b];
        int nv = decode_mask(maskr, b) - ch*CHUNK;
        s_nv = nv < 0 ? 0 : (nv > CHUNK ? CHUNK : nv);
    }
    __syncthreads();
    const int nv = s_nv;
    float* gp = g_part + ((size_t)b*NCHUNK + ch)*DD;
    if (nv == 0) {
        ((float2*)gp)[tid] = make_float2(0.f, 0.f);
        return;
    }
    const int idx = s_idx;
    const int rowbase = b*NN + ch*CHUNK;
    if (tid < CHUNK) w_s[tid] = (tid < nv) ? g_sw[(size_t)(rowbase + tid)*CC + idx] : 0.f;
    __syncthreads();
    float ax = 0.f, ay = 0.f;
    const float2* xb = (const float2*)(x + (size_t)rowbase*DD);
    int r = 0;
    for (; r + 8 <= nv; r += 8) {
        float2 vv[8];
        #pragma unroll
        for (int u = 0; u < 8; u++) vv[u] = xb[(size_t)(r+u)*256 + tid];
        #pragma unroll
        for (int u = 0; u < 8; u++) {
            float w = w_s[r+u];
            ax = fmaf(vv[u].x, w, ax);
            ay = fmaf(vv[u].y, w, ay);
        }
    }
    for (; r < nv; r++) {
        float2 vv = xb[(size_t)r*256 + tid];
        float w = w_s[r];
        ax = fmaf(vv.x, w, ax);
        ay = fmaf(vv.y, w, ay);
    }
    ((float2*)gp)[tid] = make_float2(ax, ay);
}

// one float4 of output per thread; 32 strided float4 loads each (MLP-rich)
__global__ void feat_reduce_kernel(float* __restrict__ out) {
    const int i4 = blockIdx.x*blockDim.x + threadIdx.x;   // BB*DD/4 = 4096
    const int b = i4 >> 7, d4 = i4 & 127;
    const float4* gp = (const float4*)g_part + (size_t)b*NCHUNK*128 + d4;
    float ax=0.f, ay=0.f, az=0.f, aw=0.f;
    #pragma unroll
    for (int ch = 0; ch < NCHUNK; ch++) {
        float4 q = gp[ch*128];
        ax += q.x; ay += q.y; az += q.z; aw += q.w;
    }
    ((float4*)out)[i4] = make_float4(ax, ay, az, aw);
}

extern "C" void kernel_launch(void* const* d_in, const int* in_sizes, int n_in,
                              void* d_out, int out_size) {
    const float* x       = (const float*)d_in[0];
    const int*   mask    = (const int*)d_in[1];
    const float* anchors = (const float*)d_in[2];
    float* out = (float*)d_out;

    cudaFuncSetAttribute(main_kernel, cudaFuncAttributeMaxDynamicSharedMemorySize, SM_TOTAL);

    main_kernel<<<152, 512, SM_TOTAL>>>(x, mask, anchors);
    index_kernel<<<BB, CC>>>();
    dim3 g(NCHUNK, BB);
    feat_part_kernel<<<g, 256>>>(x, mask);
    feat_reduce_kernel<<<16, 256>>>(out);
}

// round 9
// speedup vs baseline: 1.0939x; 1.0939x over previous
#include <cuda_runtime.h>
#include <cuda_fp16.h>
#include <math.h>
#include <stdint.h>

// Problem constants
#define BB 32
#define NN 4096
#define DD 512
#define CC 64
#define RTOT (BB*NN)          // 131072 rows
#define MT 32                 // rows per GEMM tile
#define NTILES (RTOT/MT)      // 4096
#define XPH 520               // x_s pitch in halves: 260 words ≡ 4 (mod 32) -> conflict-free
#define APH 520               // anchor pitch in halves
#define CHUNK 128             // rows per feature chunk
#define NCHUNK (NN/CHUNK)     // 32

// Device scratch (allocation-free rule: __device__ globals)
__device__ float  g_sw[(size_t)RTOT*CC];          // score*invnorm*valid, 32 MiB
__device__ __half g_xh[(size_t)RTOT*DD];          // x in fp16 (written by main), 128 MiB
__device__ int    g_counts[BB*CC];
__device__ int    g_index[BB];
__device__ float  g_part[(size_t)BB*NCHUNK*DD];   // 2 MiB

// mask may be int64 (jax x64) or int32. Values in [1,4096]: if int64 LE,
// word 1 (high half of elem 0) is 0.
__device__ __forceinline__ int decode_mask(const int* mr, int b) {
    return (mr[1] == 0) ? mr[2*b] : mr[b];
}

__device__ __forceinline__ void mma_f16(float& d0, float& d1, float& d2, float& d3,
                                        unsigned a0, unsigned a1, unsigned a2, unsigned a3,
                                        unsigned b0, unsigned b1) {
    asm volatile("mma.sync.aligned.m16n8k16.row.col.f32.f16.f16.f32 "
                 "{%0,%1,%2,%3}, {%4,%5,%6,%7}, {%8,%9}, {%0,%1,%2,%3};"
                 : "+f"(d0), "+f"(d1), "+f"(d2), "+f"(d3)
                 : "r"(a0), "r"(a1), "r"(a2), "r"(a3), "r"(b0), "r"(b1));
}

__global__ __launch_bounds__(512, 1)
void main_kernel(const float* __restrict__ x, const int* __restrict__ maskr,
                 const float* __restrict__ anchors) {
    extern __shared__ char smem[];
    __half*   a_h    = (__half*)smem;                    // [CC][APH] anchors fp16
    __half*   x_h    = a_h + CC*APH;                     // [MT][XPH] x tile fp16
    float*    dots_s = (float*)(x_h + MT*XPH);           // [2][MT][CC] k-half partials
    float*    anorm_s= dots_s + 2*MT*CC;                 // [CC]
    float*    norm_s = anorm_s + CC;                     // [MT]
    int*      mask_s = (int*)(norm_s + MT);              // [BB]

    const int tid  = threadIdx.x;
    const int lane = tid & 31, warp = tid >> 5;           // 16 warps

    // ---- anchors -> smem fp16, [c][k] pitch APH ----
    for (int i = tid; i < CC*DD; i += 512) {
        int c = i >> 9, k = i & (DD-1);
        a_h[c*APH + k] = __float2half_rn(anchors[i]);
    }
    if (tid < BB) mask_s[tid] = decode_mask(maskr, tid);
    if (tid < CC) {
        float s = 0.f;
        const float* ar = anchors + (size_t)tid*DD;
        #pragma unroll 8
        for (int k = 0; k < DD; k++) { float q = ar[k]; s = fmaf(q, q, s); }
        anorm_s[tid] = s;
    }
    __syncthreads();

    // warp decomposition: mslice (2) x nslice (4) x khalf (2)
    const int gid = lane >> 2, tig = lane & 3;
    const int mbase = (warp & 1) * 16;
    const int nb0   = ((warp >> 1) & 3) * 16;
    const int kh    = warp >> 3;                 // 0/1: k offset kh*256

    // load mapping: thread -> one row, 8 float4 slots
    const int lrow  = tid >> 4;                  // 0..31
    const int lslot = tid & 15;

    // ---- find first valid tile, prefetch into registers ----
    int tile = blockIdx.x;
    while (tile < NTILES) {
        int bb = (tile*MT) >> 12;
        if (((tile*MT) & (NN-1)) < mask_s[bb]) break;
        tile += gridDim.x;
    }
    float4 v[8];
    if (tile < NTILES) {
        const float4* xg = (const float4*)(x + (size_t)tile*MT*DD) + lrow*128 + lslot;
        #pragma unroll
        for (int j = 0; j < 8; j++) v[j] = xg[16*j];
    }

    while (tile < NTILES) {
        const int rowbase = tile*MT;
        const int b = rowbase >> 12;

        // ---- store tile to smem (fp16) + mirror to g_xh + row norm ----
        float ns = 0.f;
        {
            uint2* xhrow = (uint2*)(g_xh + (size_t)(rowbase + lrow)*DD);
            #pragma unroll
            for (int j = 0; j < 8; j++) {
                float4 q = v[j];
                __half2 h01 = __floats2half2_rn(q.x, q.y);
                __half2 h23 = __floats2half2_rn(q.z, q.w);
                uint2 st;
                st.x = *(unsigned*)&h01;
                st.y = *(unsigned*)&h23;
                *(uint2*)((char*)x_h + lrow*(XPH*2) + (lslot + 16*j)*8) = st;
                xhrow[lslot + 16*j] = st;
                ns = fmaf(q.x,q.x, fmaf(q.y,q.y, fmaf(q.z,q.z, fmaf(q.w,q.w, ns))));
            }
        }
        #pragma unroll
        for (int o = 8; o; o >>= 1) ns += __shfl_xor_sync(0xffffffffu, ns, o);
        if ((lane & 15) == 0) norm_s[lrow] = ns;
        __syncthreads();

        // ---- find + prefetch next valid tile (overlaps with mma) ----
        int nt = tile + gridDim.x;
        while (nt < NTILES) {
            int nb = (nt*MT) >> 12;
            if (((nt*MT) & (NN-1)) < mask_s[nb]) break;
            nt += gridDim.x;
        }
        if (nt < NTILES) {
            const float4* xg = (const float4*)(x + (size_t)nt*MT*DD) + lrow*128 + lslot;
            #pragma unroll
            for (int j = 0; j < 8; j++) v[j] = xg[16*j];
        }

        // ---- fp16 mma: warp = 16 rows x 16 cols over its k-half ----
        float d00=0,d01=0,d02=0,d03=0, d10=0,d11=0,d12=0,d13=0;
        const __half* xa = x_h + (mbase + gid)*XPH + kh*256 + 2*tig;
        const __half* b0p = a_h + (nb0 + gid)*APH     + kh*256 + 2*tig;
        const __half* b1p = a_h + (nb0 + gid + 8)*APH + kh*256 + 2*tig;
        #pragma unroll
        for (int k0 = 0; k0 < 256; k0 += 16) {
            unsigned a0 = *(const unsigned*)(xa + k0);
            unsigned a1 = *(const unsigned*)(xa + 8*XPH + k0);
            unsigned a2 = *(const unsigned*)(xa + k0 + 8);
            unsigned a3 = *(const unsigned*)(xa + 8*XPH + k0 + 8);
            unsigned b00 = *(const unsigned*)(b0p + k0);
            unsigned b01 = *(const unsigned*)(b0p + k0 + 8);
            unsigned b10 = *(const unsigned*)(b1p + k0);
            unsigned b11 = *(const unsigned*)(b1p + k0 + 8);
            mma_f16(d00,d01,d02,d03, a0,a1,a2,a3, b00,b01);
            mma_f16(d10,d11,d12,d13, a0,a1,a2,a3, b10,b11);
        }
        {
            float* dh = dots_s + kh*MT*CC;
            const int r0 = mbase + gid, r1 = r0 + 8, cb = 2*tig;
            dh[r0*CC + nb0 + cb]     = d00;
            dh[r0*CC + nb0 + cb + 1] = d01;
            dh[r1*CC + nb0 + cb]     = d02;
            dh[r1*CC + nb0 + cb + 1] = d03;
            dh[r0*CC + nb0 + 8 + cb]     = d10;
            dh[r0*CC + nb0 + 8 + cb + 1] = d11;
            dh[r1*CC + nb0 + 8 + cb]     = d12;
            dh[r1*CC + nb0 + 8 + cb + 1] = d13;
        }
        __syncthreads();

        // ---- epilogue: 2 rows per warp ----
        #pragma unroll
        for (int u = 0; u < 2; u++) {
            const int m = warp*2 + u;
            const int row = rowbase + m;
            const int n = row & (NN-1);
            const bool valid = n < mask_s[b];
            const float n2  = norm_s[m];
            const float inv = 1.f / fmaxf(sqrtf(n2), 1e-12f);
            const float sxn2 = n2 * inv * inv;
            const int cA = lane, cB = lane + 32;
            const float dA = dots_s[m*CC + cA] + dots_s[MT*CC + m*CC + cA];
            const float dB = dots_s[m*CC + cB] + dots_s[MT*CC + m*CC + cB];
            const float sqA = sxn2 + anorm_s[cA] - 2.f*dA*inv;
            const float sqB = sxn2 + anorm_s[cB] - 2.f*dB*inv;
            const float idA = rsqrtf(fmaxf(sqA, 1e-30f));
            const float idB = rsqrtf(fmaxf(sqB, 1e-30f));
            float mx = fmaxf(idA, idB);
            #pragma unroll
            for (int o = 16; o; o >>= 1) mx = fmaxf(mx, __shfl_xor_sync(0xffffffffu, mx, o));
            const float eA = __expf(idA - mx), eB = __expf(idB - mx);
            float ss = eA + eB;
            #pragma unroll
            for (int o = 16; o; o >>= 1) ss += __shfl_xor_sync(0xffffffffu, ss, o);
            const float rs = 1.f / ss;
            const size_t base = (size_t)row * CC;
            g_sw[base + cA] = valid ? eA*rs*inv : 0.f;
            g_sw[base + cB] = valid ? eB*rs*inv : 0.f;
            float bv; int bi;
            if (idB > idA) { bv = idB; bi = cB; } else { bv = idA; bi = cA; }
            #pragma unroll
            for (int o = 16; o; o >>= 1) {
                float ov = __shfl_xor_sync(0xffffffffu, bv, o);
                int   oi = __shfl_xor_sync(0xffffffffu, bi, o);
                if (ov > bv || (ov == bv && oi < bi)) { bv = ov; bi = oi; }
            }
            if (lane == 0 && valid) atomicAdd(&g_counts[b*CC + bi], 1);
        }
        __syncthreads();
        tile = nt;
    }
}

// argmax of counts per batch; also resets counts for the next graph replay
__global__ void index_kernel() {
    __shared__ int sv[CC], si[CC];
    const int b = blockIdx.x, c = threadIdx.x;
    sv[c] = g_counts[b*CC + c]; si[c] = c;
    g_counts[b*CC + c] = 0;
    __syncthreads();
    for (int o = 32; o; o >>= 1) {
        if (c < o) {
            if (sv[c+o] > sv[c] || (sv[c+o] == sv[c] && si[c+o] < si[c])) {
                sv[c] = sv[c+o]; si[c] = si[c+o];
            }
        }
        __syncthreads();
    }
    if (c == 0) g_index[b] = si[0];
}

// reads fp16 x copy (half traffic); thread tid covers d = {2*tid, 2*tid+1}
__global__ __launch_bounds__(256)
void feat_part_kernel(const int* __restrict__ maskr) {
    const int b = blockIdx.y, ch = blockIdx.x;
    const int tid = threadIdx.x;
    __shared__ float w_s[CHUNK];
    __shared__ int s_idx, s_nv;
    if (tid == 0) {
        s_idx = g_index[b];
        int nv = decode_mask(maskr, b) - ch*CHUNK;
        s_nv = nv < 0 ? 0 : (nv > CHUNK ? CHUNK : nv);
    }
    __syncthreads();
    const int nv = s_nv;
    float* gp = g_part + ((size_t)b*NCHUNK + ch)*DD;
    if (nv == 0) {
        ((float2*)gp)[tid] = make_float2(0.f, 0.f);
        return;
    }
    const int idx = s_idx;
    const int rowbase = b*NN + ch*CHUNK;
    if (tid < CHUNK) w_s[tid] = (tid < nv) ? g_sw[(size_t)(rowbase + tid)*CC + idx] : 0.f;
    __syncthreads();
    float ax = 0.f, ay = 0.f;
    const __half2* xb = (const __half2*)(g_xh + (size_t)rowbase*DD) + tid;
    int r = 0;
    for (; r + 16 <= nv; r += 16) {
        __half2 vv[16];
        #pragma unroll
        for (int u = 0; u < 16; u++) vv[u] = xb[(size_t)(r+u)*256];
        #pragma unroll
        for (int u = 0; u < 16; u++) {
            float2 f = __half22float2(vv[u]);
            float w = w_s[r+u];
            ax = fmaf(f.x, w, ax);
            ay = fmaf(f.y, w, ay);
        }
    }
    for (; r < nv; r++) {
        float2 f = __half22float2(xb[(size_t)r*256]);
        float w = w_s[r];
        ax = fmaf(f.x, w, ax);
        ay = fmaf(f.y, w, ay);
    }
    ((float2*)gp)[tid] = make_float2(ax, ay);
}

// 256 blocks x 256 threads: 64 outputs/block, 4-way chunk split + smem combine
__global__ void feat_reduce_kernel(float* __restrict__ out) {
    __shared__ float sm[256];
    const int o = threadIdx.x & 63, s = threadIdx.x >> 6;
    const int gidx = blockIdx.x*64 + o;     // 0..16383
    const int b = gidx >> 9, d = gidx & 511;
    const float* gp = g_part + ((size_t)b*NCHUNK + s*8)*DD + d;
    float sum = 0.f;
    #pragma unroll
    for (int i = 0; i < 8; i++) sum += gp[i*DD];
    sm[threadIdx.x] = sum;
    __syncthreads();
    if (s == 0) out[gidx] = sm[o] + sm[64 + o] + sm[128 + o] + sm[192 + o];
}

extern "C" void kernel_launch(void* const* d_in, const int* in_sizes, int n_in,
                              void* d_out, int out_size) {
    const float* x       = (const float*)d_in[0];
    const int*   mask    = (const int*)d_in[1];
    const float* anchors = (const float*)d_in[2];
    float* out = (float*)d_out;

    const size_t smem = (size_t)(CC*APH + MT*XPH)*sizeof(__half)
                      + (size_t)(2*MT*CC + CC + MT)*sizeof(float)
                      + BB*sizeof(int);   // ~117 KB
    cudaFuncSetAttribute(main_kernel, cudaFuncAttributeMaxDynamicSharedMemorySize, (int)smem);

    main_kernel<<<152, 512, smem>>>(x, mask, anchors);
    index_kernel<<<BB, CC>>>();
    dim3 g(NCHUNK, BB);
    feat_part_kernel<<<g, 256>>>(mask);
    feat_reduce_kernel<<<256, 256>>>(out);
}

// round 12
// speedup vs baseline: 1.1013x; 1.0068x over previous
#include <cuda_runtime.h>
#include <cuda_fp16.h>
#include <math.h>
#include <stdint.h>

// Problem constants
#define BB 32
#define NN 4096
#define DD 512
#define CC 64
#define RTOT (BB*NN)          // 131072 rows
#define MT 32                 // rows per GEMM tile
#define NTILES (RTOT/MT)      // 4096
#define XPH 520               // x_s pitch in halves: 260 words ≡ 4 (mod 32) -> conflict-free
#define APH 520               // anchor pitch in halves
#define CHUNK 128             // rows per feature chunk
#define NCHUNK (NN/CHUNK)     // 32

// Device scratch (allocation-free rule: __device__ globals)
__device__ float  g_sw[(size_t)RTOT*CC];          // score*invnorm*valid, 32 MiB
__device__ __half g_xh[(size_t)RTOT*DD];          // x in fp16 (written by main), 128 MiB
__device__ int    g_counts[BB*CC];
__device__ int    g_index[BB];
__device__ float  g_part[(size_t)BB*NCHUNK*DD];   // 2 MiB

// mask may be int64 (jax x64) or int32. Values in [1,4096]: if int64 LE,
// word 1 (high half of elem 0) is 0.
__device__ __forceinline__ int decode_mask(const int* mr, int b) {
    return (mr[1] == 0) ? mr[2*b] : mr[b];
}

// fp16-accumulate mma: C/D packed as 2x half2 registers
__device__ __forceinline__ void mma_f16acc(unsigned& c0, unsigned& c1,
                                           unsigned a0, unsigned a1, unsigned a2, unsigned a3,
                                           unsigned b0, unsigned b1) {
    asm volatile("mma.sync.aligned.m16n8k16.row.col.f16.f16.f16.f16 "
                 "{%0,%1}, {%2,%3,%4,%5}, {%6,%7}, {%0,%1};"
                 : "+r"(c0), "+r"(c1)
                 : "r"(a0), "r"(a1), "r"(a2), "r"(a3), "r"(b0), "r"(b1));
}

__global__ __launch_bounds__(512, 1)
void main_kernel(const float* __restrict__ x, const int* __restrict__ maskr,
                 const float* __restrict__ anchors) {
    extern __shared__ char smem[];
    __half*   a_h    = (__half*)smem;                    // [CC][APH] anchors fp16
    __half*   x_h    = a_h + CC*APH;                     // [MT][XPH] x tile fp16
    float*    dots_s = (float*)(x_h + MT*XPH);           // [2][MT][CC] k-half partials
    float*    anorm_s= dots_s + 2*MT*CC;                 // [CC]
    float*    norm_s = anorm_s + CC;                     // [MT]
    int*      mask_s = (int*)(norm_s + MT);              // [BB]

    const int tid  = threadIdx.x;
    const int lane = tid & 31, warp = tid >> 5;           // 16 warps

    // ---- anchors -> smem fp16, [c][k] pitch APH ----
    for (int i = tid; i < CC*DD; i += 512) {
        int c = i >> 9, k = i & (DD-1);
        a_h[c*APH + k] = __float2half_rn(anchors[i]);
    }
    if (tid < BB) mask_s[tid] = decode_mask(maskr, tid);
    if (tid < CC) {
        float s = 0.f;
        const float* ar = anchors + (size_t)tid*DD;
        #pragma unroll 8
        for (int k = 0; k < DD; k++) { float q = ar[k]; s = fmaf(q, q, s); }
        anorm_s[tid] = s;
    }
    __syncthreads();

    // warp decomposition: mslice (2) x nslice (4) x khalf (2)
    const int gid = lane >> 2, tig = lane & 3;
    const int mbase = (warp & 1) * 16;
    const int nb0   = ((warp >> 1) & 3) * 16;
    const int kh    = warp >> 3;                 // 0/1: k offset kh*256

    // load mapping: thread -> one row, 8 float4 slots
    const int lrow  = tid >> 4;                  // 0..31
    const int lslot = tid & 15;

    // ---- find first valid tile, prefetch into registers ----
    int tile = blockIdx.x;
    while (tile < NTILES) {
        int bb = (tile*MT) >> 12;
        if (((tile*MT) & (NN-1)) < mask_s[bb]) break;
        tile += gridDim.x;
    }
    float4 v[8];
    if (tile < NTILES) {
        const float4* xg = (const float4*)(x + (size_t)tile*MT*DD) + lrow*128 + lslot;
        #pragma unroll
        for (int j = 0; j < 8; j++) v[j] = xg[16*j];
    }

    while (tile < NTILES) {
        const int rowbase = tile*MT;
        const int b = rowbase >> 12;

        // ---- store tile to smem (fp16) + mirror to g_xh + row norm ----
        float ns = 0.f;
        {
            uint2* xhrow = (uint2*)(g_xh + (size_t)(rowbase + lrow)*DD);
            #pragma unroll
            for (int j = 0; j < 8; j++) {
                float4 q = v[j];
                __half2 h01 = __floats2half2_rn(q.x, q.y);
                __half2 h23 = __floats2half2_rn(q.z, q.w);
                uint2 st;
                st.x = *(unsigned*)&h01;
                st.y = *(unsigned*)&h23;
                *(uint2*)((char*)x_h + lrow*(XPH*2) + (lslot + 16*j)*8) = st;
                xhrow[lslot + 16*j] = st;
                ns = fmaf(q.x,q.x, fmaf(q.y,q.y, fmaf(q.z,q.z, fmaf(q.w,q.w, ns))));
            }
        }
        #pragma unroll
        for (int o = 8; o; o >>= 1) ns += __shfl_xor_sync(0xffffffffu, ns, o);
        if ((lane & 15) == 0) norm_s[lrow] = ns;
        __syncthreads();

        // ---- find + prefetch next valid tile (overlaps with mma) ----
        int nt = tile + gridDim.x;
        while (nt < NTILES) {
            int nb = (nt*MT) >> 12;
            if (((nt*MT) & (NN-1)) < mask_s[nb]) break;
            nt += gridDim.x;
        }
        if (nt < NTILES) {
            const float4* xg = (const float4*)(x + (size_t)nt*MT*DD) + lrow*128 + lslot;
            #pragma unroll
            for (int j = 0; j < 8; j++) v[j] = xg[16*j];
        }

        // ---- fp16 mma, fp16 accumulate in chains of 4, fp32 promotion ----
        float d00=0,d01=0,d02=0,d03=0, d10=0,d11=0,d12=0,d13=0;
        const __half* xa  = x_h + (mbase + gid)*XPH + kh*256 + 2*tig;
        const __half* b0p = a_h + (nb0 + gid)*APH     + kh*256 + 2*tig;
        const __half* b1p = a_h + (nb0 + gid + 8)*APH + kh*256 + 2*tig;
        #pragma unroll
        for (int g = 0; g < 4; g++) {
            unsigned e00=0, e01=0, e10=0, e11=0;
            #pragma unroll
            for (int s = 0; s < 4; s++) {
                const int k0 = (g*4 + s)*16;
                unsigned a0 = *(const unsigned*)(xa + k0);
                unsigned a1 = *(const unsigned*)(xa + 8*XPH + k0);
                unsigned a2 = *(const unsigned*)(xa + k0 + 8);
                unsigned a3 = *(const unsigned*)(xa + 8*XPH + k0 + 8);
                unsigned b00 = *(const unsigned*)(b0p + k0);
                unsigned b01 = *(const unsigned*)(b0p + k0 + 8);
                unsigned b10 = *(const unsigned*)(b1p + k0);
                unsigned b11 = *(const unsigned*)(b1p + k0 + 8);
                mma_f16acc(e00, e01, a0,a1,a2,a3, b00,b01);
                mma_f16acc(e10, e11, a0,a1,a2,a3, b10,b11);
            }
            {
                float2 f;
                f = __half22float2(*(__half2*)&e00); d00 += f.x; d01 += f.y;
                f = __half22float2(*(__half2*)&e01); d02 += f.x; d03 += f.y;
                f = __half22float2(*(__half2*)&e10); d10 += f.x; d11 += f.y;
                f = __half22float2(*(__half2*)&e11); d12 += f.x; d13 += f.y;
            }
        }
        {
            float* dh = dots_s + kh*MT*CC;
            const int r0 = mbase + gid, r1 = r0 + 8, cb = 2*tig;
            dh[r0*CC + nb0 + cb]     = d00;
            dh[r0*CC + nb0 + cb + 1] = d01;
            dh[r1*CC + nb0 + cb]     = d02;
            dh[r1*CC + nb0 + cb + 1] = d03;
            dh[r0*CC + nb0 + 8 + cb]     = d10;
            dh[r0*CC + nb0 + 8 + cb + 1] = d11;
            dh[r1*CC + nb0 + 8 + cb]     = d12;
            dh[r1*CC + nb0 + 8 + cb + 1] = d13;
        }
        __syncthreads();

        // ---- epilogue: 2 rows per warp; softmax without max-shift ----
        // (invd <= 1/11.6 always since ||anchor|| >= 12.6, ||xn|| = 1 -> no overflow)
        #pragma unroll
        for (int u = 0; u < 2; u++) {
            const int m = warp*2 + u;
            const int row = rowbase + m;
            const int n = row & (NN-1);
            const bool valid = n < mask_s[b];
            const float n2  = norm_s[m];
            const float inv = 1.f / fmaxf(sqrtf(n2), 1e-12f);
            const float sxn2 = n2 * inv * inv;
            const int cA = lane, cB = lane + 32;
            const float dA = dots_s[m*CC + cA] + dots_s[MT*CC + m*CC + cA];
            const float dB = dots_s[m*CC + cB] + dots_s[MT*CC + m*CC + cB];
            const float sqA = sxn2 + anorm_s[cA] - 2.f*dA*inv;
            const float sqB = sxn2 + anorm_s[cB] - 2.f*dB*inv;
            const float idA = rsqrtf(fmaxf(sqA, 1e-30f));
            const float idB = rsqrtf(fmaxf(sqB, 1e-30f));
            const float eA = __expf(idA), eB = __expf(idB);
            float ss = eA + eB;
            #pragma unroll
            for (int o = 16; o; o >>= 1) ss += __shfl_xor_sync(0xffffffffu, ss, o);
            const float rs = 1.f / ss;
            const size_t base = (size_t)row * CC;
            g_sw[base + cA] = valid ? eA*rs*inv : 0.f;
            g_sw[base + cB] = valid ? eB*rs*inv : 0.f;
            float bv; int bi;
            if (idB > idA) { bv = idB; bi = cB; } else { bv = idA; bi = cA; }
            #pragma unroll
            for (int o = 16; o; o >>= 1) {
                float ov = __shfl_xor_sync(0xffffffffu, bv, o);
                int   oi = __shfl_xor_sync(0xffffffffu, bi, o);
                if (ov > bv || (ov == bv && oi < bi)) { bv = ov; bi = oi; }
            }
            if (lane == 0 && valid) atomicAdd(&g_counts[b*CC + bi], 1);
        }
        __syncthreads();
        tile = nt;
    }
}

// argmax of counts per batch; also resets counts for the next graph replay
__global__ void index_kernel() {
    __shared__ int sv[CC], si[CC];
    const int b = blockIdx.x, c = threadIdx.x;
    sv[c] = g_counts[b*CC + c]; si[c] = c;
    g_counts[b*CC + c] = 0;
    __syncthreads();
    for (int o = 32; o; o >>= 1) {
        if (c < o) {
            if (sv[c+o] > sv[c] || (sv[c+o] == sv[c] && si[c+o] < si[c])) {
                sv[c] = sv[c+o]; si[c] = si[c+o];
            }
        }
        __syncthreads();
    }
    if (c == 0) g_index[b] = si[0];
}

// reads fp16 x copy (half traffic); thread tid covers d = {2*tid, 2*tid+1}
__global__ __launch_bounds__(256)
void feat_part_kernel(const int* __restrict__ maskr) {
    const int b = blockIdx.y, ch = blockIdx.x;
    const int tid = threadIdx.x;
    __shared__ float w_s[CHUNK];
    __shared__ int s_idx, s_nv;
    if (tid == 0) {
        s_idx = g_index[b];
        int nv = decode_mask(maskr, b) - ch*CHUNK;
        s_nv = nv < 0 ? 0 : (nv > CHUNK ? CHUNK : nv);
    }
    __syncthreads();
    const int nv = s_nv;
    float* gp = g_part + ((size_t)b*NCHUNK + ch)*DD;
    if (nv == 0) {
        ((float2*)gp)[tid] = make_float2(0.f, 0.f);
        return;
    }
    const int idx = s_idx;
    const int rowbase = b*NN + ch*CHUNK;
    if (tid < CHUNK) w_s[tid] = (tid < nv) ? g_sw[(size_t)(rowbase + tid)*CC + idx] : 0.f;
    __syncthreads();
    float ax = 0.f, ay = 0.f;
    const __half2* xb = (const __half2*)(g_xh + (size_t)rowbase*DD) + tid;
    int r = 0;
    for (; r + 16 <= nv; r += 16) {
        __half2 vv[16];
        #pragma unroll
        for (int u = 0; u < 16; u++) vv[u] = xb[(size_t)(r+u)*256];
        #pragma unroll
        for (int u = 0; u < 16; u++) {
            float2 f = __half22float2(vv[u]);
            float w = w_s[r+u];
            ax = fmaf(f.x, w, ax);
            ay = fmaf(f.y, w, ay);
        }
    }
    for (; r < nv; r++) {
        float2 f = __half22float2(xb[(size_t)r*256]);
        float w = w_s[r];
        ax = fmaf(f.x, w, ax);
        ay = fmaf(f.y, w, ay);
    }
    ((float2*)gp)[tid] = make_float2(ax, ay);
}

// 256 blocks x 256 threads: 64 outputs/block, 4-way chunk split + smem combine
__global__ void feat_reduce_kernel(float* __restrict__ out) {
    __shared__ float sm[256];
    const int o = threadIdx.x & 63, s = threadIdx.x >> 6;
    const int gidx = blockIdx.x*64 + o;     // 0..16383
    const int b = gidx >> 9, d = gidx & 511;
    const float* gp = g_part + ((size_t)b*NCHUNK + s*8)*DD + d;
    float sum = 0.f;
    #pragma unroll
    for (int i = 0; i < 8; i++) sum += gp[i*DD];
    sm[threadIdx.x] = sum;
    __syncthreads();
    if (s == 0) out[gidx] = sm[o] + sm[64 + o] + sm[128 + o] + sm[192 + o];
}

extern "C" void kernel_launch(void* const* d_in, const int* in_sizes, int n_in,
                              void* d_out, int out_size) {
    const float* x       = (const float*)d_in[0];
    const int*   mask    = (const int*)d_in[1];
    const float* anchors = (const float*)d_in[2];
    float* out = (float*)d_out;

    const size_t smem = (size_t)(CC*APH + MT*XPH)*sizeof(__half)
                      + (size_t)(2*MT*CC + CC + MT)*sizeof(float)
                      + BB*sizeof(int);   // ~117 KB
    cudaFuncSetAttribute(main_kernel, cudaFuncAttributeMaxDynamicSharedMemorySize, (int)smem);

    main_kernel<<<152, 512, smem>>>(x, mask, anchors);
    index_kernel<<<BB, CC>>>();
    dim3 g(NCHUNK, BB);
    feat_part_kernel<<<g, 256>>>(mask);
    feat_reduce_kernel<<<256, 256>>>(out);
}